// round 1
// baseline (speedup 1.0000x reference)
#include <cuda_runtime.h>
#include <math.h>

// Spherization: per row r (512 features):
//   ang_j = (PI - 2*phiL) * sigmoid(scaling * x[r,j]) + phiL
//   s_j   = |sin(ang_j)| + 1e-6   (sin>0 on the angle range)
//   c_j   = sign(cos(ang_j)) * (|cos(ang_j)| + 1e-6)
//   out[r,k]   = radius * (prod_{j<k} s_j) * c_k          , k = 0..511
//   out[r,512] = radius * prod_{j=0..511} s_j
// One warp per row. Lane l owns elements k = 128*j + 4*l + m (j=0..3, m=0..3):
// float4-coalesced loads, 4 chained warp scans, SMEM-staged coalesced stores.

#define NFEAT 512
#define ROW_OUT 513
#define SROW_PITCH 520   // floats; 520*4 bytes, 16B-aligned pitch
#define WARPS_PER_BLOCK 8

__global__ __launch_bounds__(WARPS_PER_BLOCK * 32)
void spherization_kernel(const float* __restrict__ x,
                         const float* __restrict__ scaling_p,
                         const float* __restrict__ radius_p,
                         float* __restrict__ out,
                         int nrows, float A, float phiL)
{
    __shared__ float sbuf[WARPS_PER_BLOCK * SROW_PITCH];

    const int wib  = threadIdx.x >> 5;
    const int lane = threadIdx.x & 31;
    const int row  = blockIdx.x * WARPS_PER_BLOCK + wib;
    if (row >= nrows) return;

    const float scaling = __ldg(scaling_p);
    const float radius  = __ldg(radius_p);
    const float EPSf = 1e-6f;

    const float4* xr = reinterpret_cast<const float4*>(x + (size_t)row * NFEAT);
    float* srow = sbuf + wib * SROW_PITCH;

    float carry = radius;   // radius * (product of all elements in completed blocks)

    #pragma unroll
    for (int j = 0; j < 4; j++) {
        float4 v4 = xr[lane + 32 * j];   // elements 128j + 4*lane + {0,1,2,3}
        float vv[4] = {v4.x, v4.y, v4.z, v4.w};
        float sv[4], cv[4];
        #pragma unroll
        for (int m = 0; m < 4; m++) {
            float z   = scaling * vv[m];
            float e   = __expf(-z);
            float sg  = __fdividef(1.0f, 1.0f + e);   // sigmoid, MUFU EX2 + RCP
            float ang = fmaf(A, sg, phiL);            // in [phiL, pi - phiL]
            float sn  = __sinf(ang);                  // > 0
            float cs  = __cosf(ang);
            sv[m] = sn + EPSf;
            cv[m] = copysignf(fabsf(cs) + EPSf, cs);
        }
        // local exclusive prefixes within the 4 owned elements
        float e1  = sv[0];
        float e2  = e1 * sv[1];
        float e3  = e2 * sv[2];
        float tot = e3 * sv[3];

        // warp-inclusive scan of per-lane block totals
        float incl = tot;
        #pragma unroll
        for (int d = 1; d < 32; d <<= 1) {
            float t = __shfl_up_sync(0xFFFFFFFFu, incl, d);
            if (lane >= d) incl *= t;
        }
        float excl = __shfl_up_sync(0xFFFFFFFFu, incl, 1);
        if (lane == 0) excl = 1.0f;

        float bp = carry * excl;  // radius * prod of everything before element 128j+4*lane

        float4 o;
        o.x = bp * cv[0];
        o.y = (bp * e1) * cv[1];
        o.z = (bp * e2) * cv[2];
        o.w = (bp * e3) * cv[3];
        reinterpret_cast<float4*>(srow)[lane + 32 * j] = o;

        carry *= __shfl_sync(0xFFFFFFFFu, incl, 31);
    }
    if (lane == 0) srow[NFEAT] = carry;   // out[512] = radius * full product
    __syncwarp();

    // coalesced copy SMEM row -> GMEM (row pitch 513 floats, can't vectorize)
    float* orow = out + (size_t)row * ROW_OUT;
    #pragma unroll
    for (int it = 0; it < 17; it++) {
        int c = lane + 32 * it;
        if (c < ROW_OUT) orow[c] = srow[c];
    }
}

extern "C" void kernel_launch(void* const* d_in, const int* in_sizes, int n_in,
                              void* d_out, int out_size)
{
    // inputs: x [B,512] f32, scaling f32 scalar, radius f32 scalar (in that order);
    // be robust: x is the large tensor.
    int xi = 0;
    for (int i = 0; i < n_in; i++) if (in_sizes[i] > in_sizes[xi]) xi = i;
    int others[2]; int no = 0;
    for (int i = 0; i < n_in && no < 2; i++) if (i != xi) others[no++] = i;

    const float* x   = (const float*)d_in[xi];
    const float* sc  = (const float*)d_in[others[0]];   // scaling
    const float* rad = (const float*)d_in[others[1]];   // radius

    float* out = (float*)d_out;
    int nrows = in_sizes[xi] / NFEAT;

    // constants computed in double, matching the reference's truncated PI
    const double PI_d = 3.141592;
    double phiL = asin(pow(1e-6, 1.0 / 512.0));
    double phiU = PI_d / 2.0 * (1.0 - 0.01);
    if (phiU < phiL) phiL = phiU;
    float A = (float)(PI_d - 2.0 * phiL);

    int blocks = (nrows + WARPS_PER_BLOCK - 1) / WARPS_PER_BLOCK;
    spherization_kernel<<<blocks, WARPS_PER_BLOCK * 32>>>(
        x, sc, rad, out, nrows, A, (float)phiL);
}